// round 15
// baseline (speedup 1.0000x reference)
#include <cuda_runtime.h>
#include <math_constants.h>
#include <stdint.h>

// Problem constants
#define B_   64
#define L_   1024
#define D_   64
#define BQ   32          // q rows per CTA
#define CH   128         // keys per chunk
#define NCH  (L_ / CH)   // 8
#define THREADS 512

#define SP   1028        // sS pitch (mod 32 == 4 -> conflict-free scalar frag loads)
#define QP2  136         // Q pitch, hi/lo interleaved (mod 32 == 8 -> conflict-free LDS.64)
#define KP   68          // K-phase pitch inside buf (mod 32 == 4)
#define VP   72          // V-phase pitch inside buf (mod 32 == 8)
#define BUFSZ (CH * VP)  // 9216 floats per buffer

// smem (floats): sS[32][1028] | sQ[32][136] (hi/lo interleaved) | buf[2][BUFSZ] | sSum[32] | sInv[32]
#define OFF_SQ  (BQ * SP)
#define OFF_BUF (OFF_SQ + BQ * QP2)
#define OFF_SUM (OFF_BUF + 2 * BUFSZ)
#define OFF_INV (OFF_SUM + 32)
#define SMEM_FLOATS (OFF_INV + 32)

// 0 = mask is 1 byte/element, 1 = mask is 4 bytes/element (int32 or float32)
__device__ int g_mask_w4;

__global__ void detect_mask_kernel(const unsigned* m)
{
    __shared__ int ok;
    if (threadIdx.x == 0) ok = 1;
    __syncthreads();
    #pragma unroll
    for (int p = 0; p < 16; p++) {
        unsigned v = m[threadIdx.x + p * 256];
        if (!(v == 0u || v == 1u || v == 0x3F800000u)) ok = 0;
    }
    __syncthreads();
    if (threadIdx.x == 0) g_mask_w4 = ok;
}

__device__ __forceinline__ float tf32r(float x) {
    uint32_t u;
    asm("cvt.rna.tf32.f32 %0, %1;" : "=r"(u) : "f"(x));
    return __uint_as_float(u);
}

__device__ __forceinline__ void cp_async16(uint32_t saddr, const void* gaddr) {
    asm volatile("cp.async.cg.shared.global [%0], [%1], 16;" :: "r"(saddr), "l"(gaddr));
}
__device__ __forceinline__ void cp_commit() { asm volatile("cp.async.commit_group;"); }
template<int N> __device__ __forceinline__ void cp_wait() {
    asm volatile("cp.async.wait_group %0;" :: "n"(N));
}

#define MMA_TF32(c, A0, A1, A2, A3, Bb0, Bb1)                                   \
    asm volatile(                                                               \
        "mma.sync.aligned.m16n8k8.row.col.f32.tf32.tf32.f32 "                   \
        "{%0,%1,%2,%3}, {%4,%5,%6,%7}, {%8,%9}, {%0,%1,%2,%3};"                 \
        : "+f"((c)[0]), "+f"((c)[1]), "+f"((c)[2]), "+f"((c)[3])                \
        : "r"(__float_as_uint(A0)), "r"(__float_as_uint(A1)),                   \
          "r"(__float_as_uint(A2)), "r"(__float_as_uint(A3)),                   \
          "r"(__float_as_uint(Bb0)), "r"(__float_as_uint(Bb1)))

__global__ __launch_bounds__(THREADS, 1)
void attn_tf32_kernel(const float* __restrict__ q,
                      const float* __restrict__ k,
                      const float* __restrict__ v,
                      const void* __restrict__ maskp,
                      float* __restrict__ outO,
                      float* __restrict__ outA)
{
    extern __shared__ float smem[];
    float* sS   = smem;
    float* sQ   = smem + OFF_SQ;
    float* buf  = smem + OFF_BUF;
    float* sSum = smem + OFF_SUM;
    float* sInv = smem + OFF_INV;

    const int b   = blockIdx.y;
    const int q0  = blockIdx.x * BQ;
    const int t    = threadIdx.x;
    const int warp = t >> 5;
    const int lane = t & 31;
    const int gid  = lane >> 2;   // groupID 0..7
    const int tig  = lane & 3;    // thread-in-group 0..3

    const int mask_w4 = g_mask_w4;

    const float* qb = q + ((size_t)b * L_ + q0) * D_;
    const float* kb = k + (size_t)b * L_ * D_;
    const float* vb = v + (size_t)b * L_ * D_;
    const size_t mbase = ((size_t)b * L_ + q0) * (size_t)L_;
    const unsigned char* mb8 = (const unsigned char*)maskp + mbase;
    const unsigned*      mb4 = (const unsigned*)maskp + mbase;
    float* oOb = outO + ((size_t)b * L_ + q0) * D_;
    float* oAb = outA + ((size_t)b * L_ + q0) * (size_t)L_;

    if (t < 32) sSum[t] = 0.f;

    // ---- stage Q (32 x 64): scale by 1/8 (exact), split hi/lo interleaved ----
    {
        int r = t >> 4, c4 = t & 15;                 // 512 float4 = whole tile
        float4 f = ((const float4*)qb)[t];
        f.x *= 0.125f; f.y *= 0.125f; f.z *= 0.125f; f.w *= 0.125f;
        float hx = tf32r(f.x), hy = tf32r(f.y), hz = tf32r(f.z), hw = tf32r(f.w);
        float4 lo4 = make_float4(hx, tf32r(f.x - hx), hy, tf32r(f.y - hy));
        float4 hi4 = make_float4(hz, tf32r(f.z - hz), hw, tf32r(f.w - hw));
        float* dst = &sQ[r * QP2 + 8 * c4];
        *(float4*)dst       = lo4;   // {hx,lx,hy,ly}
        *(float4*)(dst + 4) = hi4;   // {hz,lz,hw,lw}
    }

    // ---- prefetch K chunk 0 (128 keys x 64 d, pitch KP) ----
    #pragma unroll
    for (int p = 0; p < 4; p++) {
        int idx = t + p * THREADS;                   // 2048 float4
        int r = idx >> 4, c4 = idx & 15;
        uint32_t sa = (uint32_t)__cvta_generic_to_shared(&buf[r * KP + c4 * 4]);
        cp_async16(sa, &kb[r * 64 + c4 * 4]);
    }
    cp_commit();

    // ================= Phase 1: sS = exp(mask(QK^T / 8)) + row sums =================
    const int mw = warp & 1;           // m-group: rows mw*16 .. +15
    const int nw = warp >> 1;          // n-group: keys nw*16 .. +15 within chunk
    const int r0 = mw * 16;
    const int n0 = nw * 16;

    for (int c = 0; c < NCH; c++) {
        const int cur = c & 1, nxt = cur ^ 1;
        if (c + 1 < NCH) {
            #pragma unroll
            for (int p = 0; p < 4; p++) {
                int idx = t + p * THREADS;
                int r = idx >> 4, c4 = idx & 15;
                uint32_t sa = (uint32_t)__cvta_generic_to_shared(
                    &buf[nxt * BUFSZ + r * KP + c4 * 4]);
                cp_async16(sa, &kb[((c + 1) * CH + r) * 64 + c4 * 4]);
            }
            cp_commit();
            cp_wait<1>();
        } else {
            cp_wait<0>();
        }
        __syncthreads();

        const float* kbuf = &buf[cur * BUFSZ];
        float acc[2][4] = {{0.f,0.f,0.f,0.f},{0.f,0.f,0.f,0.f}};

        #pragma unroll
        for (int ks = 0; ks < 8; ks++) {
            const int k0 = ks * 8;
            float2 A0 = *(const float2*)&sQ[(r0 + gid)     * QP2 + 2 * (k0 + tig)];
            float2 A1 = *(const float2*)&sQ[(r0 + 8 + gid) * QP2 + 2 * (k0 + tig)];
            float2 A2 = *(const float2*)&sQ[(r0 + gid)     * QP2 + 2 * (k0 + 4 + tig)];
            float2 A3 = *(const float2*)&sQ[(r0 + 8 + gid) * QP2 + 2 * (k0 + 4 + tig)];
            #pragma unroll
            for (int j = 0; j < 2; j++) {
                const float* kr = &kbuf[(n0 + 8 * j + gid) * KP + k0 + tig];
                float br0 = kr[0], br1 = kr[4];
                float bh0 = tf32r(br0), bl0 = tf32r(br0 - bh0);
                float bh1 = tf32r(br1), bl1 = tf32r(br1 - bh1);
                MMA_TF32(acc[j], A0.x, A1.x, A2.x, A3.x, bh0, bh1);
                MMA_TF32(acc[j], A0.y, A1.y, A2.y, A3.y, bh0, bh1);
                MMA_TF32(acc[j], A0.x, A1.x, A2.x, A3.x, bl0, bl1);
            }
        }

        // epilogue: mask -> exp -> store sS tf32-rounded (unnormalized), row sums
        float s_lo = 0.f, s_hi = 0.f;
        #pragma unroll
        for (int j = 0; j < 2; j++) {
            int colb = c * CH + n0 + 8 * j + 2 * tig;
            float st[4];
            #pragma unroll
            for (int e = 0; e < 4; e++) {
                int row = r0 + gid + (e >> 1) * 8;
                int g   = colb + (e & 1);
                unsigned midx = (unsigned)row * L_ + (unsigned)g;
                bool msk = mask_w4 ? (mb4[midx] != 0u) : (mb8[midx] != 0);
                float ex = msk ? 0.f : __expf(acc[j][e]);
                st[e] = tf32r(ex);
                if (e < 2) s_lo += ex; else s_hi += ex;
            }
            *(float2*)&sS[(r0 + gid)     * SP + colb] = make_float2(st[0], st[1]);
            *(float2*)&sS[(r0 + 8 + gid) * SP + colb] = make_float2(st[2], st[3]);
        }
        s_lo += __shfl_xor_sync(0xFFFFFFFFu, s_lo, 1);
        s_lo += __shfl_xor_sync(0xFFFFFFFFu, s_lo, 2);
        s_hi += __shfl_xor_sync(0xFFFFFFFFu, s_hi, 1);
        s_hi += __shfl_xor_sync(0xFFFFFFFFu, s_hi, 2);
        if (tig == 0) {
            atomicAdd(&sSum[r0 + gid],     s_lo);
            atomicAdd(&sSum[r0 + 8 + gid], s_hi);
        }
        __syncthreads();
    }

    // row reciprocals
    if (t < 32) sInv[t] = 1.f / sSum[t];

    // ---- prefetch V chunk 0 (pitch VP) while attn is written ----
    #pragma unroll
    for (int p = 0; p < 4; p++) {
        int idx = t + p * THREADS;
        int r = idx >> 4, c4 = idx & 15;
        uint32_t sa = (uint32_t)__cvta_generic_to_shared(&buf[r * VP + c4 * 4]);
        cp_async16(sa, &vb[r * 64 + c4 * 4]);
    }
    cp_commit();
    __syncthreads();   // sInv visible

    // ---- write normalized attn (sS stays unnormalized for PV) ----
    #pragma unroll
    for (int rr = 0; rr < 2; rr++) {
        int row = warp * 2 + rr;
        float inv = sInv[row];
        const float* srow = &sS[row * SP];
        float* arow = &oAb[(size_t)row * L_];
        for (int j = lane; j < L_; j += 32)
            arow[j] = srow[j] * inv;
    }

    // ================= Phase 2: O = P @ V (single-pass tf32, m16n16) =================
    const int kw  = warp >> 3;         // 0/1: k-half within chunk (ks 0-7 / 8-15)
    const int nw2 = (warp >> 1) & 3;   // 4 d-col groups of 16
    const int r0v = mw * 16;
    const int n0v = nw2 * 16;
    const int ksb = kw * 8;
    float acc2[2][4] = {{0.f,0.f,0.f,0.f},{0.f,0.f,0.f,0.f}};

    for (int c = 0; c < NCH; c++) {
        const int cur = c & 1, nxt = cur ^ 1;
        if (c + 1 < NCH) {
            #pragma unroll
            for (int p = 0; p < 4; p++) {
                int idx = t + p * THREADS;
                int r = idx >> 4, c4 = idx & 15;
                uint32_t sa = (uint32_t)__cvta_generic_to_shared(
                    &buf[nxt * BUFSZ + r * VP + c4 * 4]);
                cp_async16(sa, &vb[((c + 1) * CH + r) * 64 + c4 * 4]);
            }
            cp_commit();
            cp_wait<1>();
        } else {
            cp_wait<0>();
        }
        __syncthreads();

        const float* vbuf = &buf[cur * BUFSZ];

        #pragma unroll
        for (int ks = 0; ks < 8; ks++) {
            const int kc = (ksb + ks) * 8;          // key offset within chunk
            const int kg = c * CH + kc;             // global key (sS col)
            float a0 = sS[(r0v + gid)     * SP + kg + tig];      // pre-rounded tf32
            float a1 = sS[(r0v + 8 + gid) * SP + kg + tig];
            float a2 = sS[(r0v + gid)     * SP + kg + 4 + tig];
            float a3 = sS[(r0v + 8 + gid) * SP + kg + 4 + tig];
            #pragma unroll
            for (int j = 0; j < 2; j++) {
                float br0 = vbuf[(kc + tig)     * VP + n0v + 8 * j + gid];
                float br1 = vbuf[(kc + 4 + tig) * VP + n0v + 8 * j + gid];
                float bh0 = tf32r(br0), bh1 = tf32r(br1);
                MMA_TF32(acc2[j], a0, a1, a2, a3, bh0, bh1);
            }
        }
        __syncthreads();
    }

    // ---- reduce k-halves via smem scratch (reuse sQ), scale by 1/sum, write O ----
    float* scr = sQ;   // [32][64]
    if (kw == 1) {
        #pragma unroll
        for (int j = 0; j < 2; j++) {
            #pragma unroll
            for (int e = 0; e < 4; e++) {
                int row = r0v + gid + (e >> 1) * 8;
                int col = n0v + 8 * j + 2 * tig + (e & 1);
                scr[row * 64 + col] = acc2[j][e];
            }
        }
    }
    __syncthreads();
    if (kw == 0) {
        #pragma unroll
        for (int j = 0; j < 2; j++) {
            #pragma unroll
            for (int e = 0; e < 4; e++) {
                int row = r0v + gid + (e >> 1) * 8;
                int col = n0v + 8 * j + 2 * tig + (e & 1);
                float o = (acc2[j][e] + scr[row * 64 + col]) * sInv[row];
                oOb[(size_t)row * D_ + col] = o;
            }
        }
    }
}

extern "C" void kernel_launch(void* const* d_in, const int* in_sizes, int n_in,
                              void* d_out, int out_size)
{
    const float* q = (const float*)d_in[0];
    const float* k = (const float*)d_in[1];
    const float* v = (const float*)d_in[2];
    const void*  mask = d_in[3];

    float* outO = (float*)d_out;                               // (B, Lq, D)
    float* outA = outO + (size_t)B_ * L_ * D_;                 // (B, Lq, Lk)

    const int smem_bytes = SMEM_FLOATS * (int)sizeof(float);   // ~223 KB
    cudaFuncSetAttribute(attn_tf32_kernel,
                         cudaFuncAttributeMaxDynamicSharedMemorySize, smem_bytes);

    detect_mask_kernel<<<1, 256>>>((const unsigned*)mask);

    dim3 grid(L_ / BQ, B_);   // (32, 64)
    attn_tf32_kernel<<<grid, THREADS, smem_bytes>>>(q, k, v, mask, outO, outA);
}